// round 13
// baseline (speedup 1.0000x reference)
#include <cuda_runtime.h>
#include <math.h>
#include <float.h>
#include <stdint.h>

#define BATCH 32
#define NTOK  576
#define NK    577      // N + 1 (with CLS)
#define CH    1024
#define LTOP  72       // N/8
#define NCOMPL 504     // N - L
#define KCL   32
#define NSEG  12
#define SEGTOK (NCOMPL / NSEG)   // 42
#define KSPLIT 8

// ---------------- device scratch (static, allocation-free) ----------------
__device__ float g_logits[BATCH][NK];
__device__ float g_ninv[BATCH][NTOK];
__device__ float g_attn[BATCH][NTOK];
__device__ int   g_idx[BATCH][LTOP];
__device__ int   g_compl[BATCH][NCOMPL];
__device__ float g_sim[KSPLIT][BATCH][LTOP][NTOK];
__device__ float g_xpart[BATCH][NSEG][CH];
__device__ int   g_cnt[BATCH];

#define CP_ASYNC16(dst, src) \
    asm volatile("cp.async.cg.shared.global [%0], [%1], 16;" :: "r"(dst), "l"(src) : "memory")
#define CP_COMMIT() asm volatile("cp.async.commit_group;" ::: "memory")
#define CP_WAIT(n)  asm volatile("cp.async.wait_group %0;" :: "n"(n) : "memory")

__device__ __forceinline__ uint32_t smem_u32(const void* p) {
    uint32_t a;
    asm("{ .reg .u64 t; cvta.to.shared.u64 t, %1; cvt.u32.u64 %0, t; }" : "=r"(a) : "l"(p));
    return a;
}

// ---------------- K1: logits (q0 . key_r) and per-row inv-norms (grid-wide) -------------
__global__ __launch_bounds__(256) void k_logits(const float* __restrict__ keys,
                                                const float* __restrict__ queries) {
    int gw   = (blockIdx.x * blockDim.x + threadIdx.x) >> 5;
    int lane = threadIdx.x & 31;
    if (gw >= BATCH * NK) return;
    int b = gw / NK;
    int r = gw - b * NK;
    const float4* q = (const float4*)(queries + (size_t)b * NK * CH);
    const float4* k = (const float4*)(keys + ((size_t)b * NK + r) * CH);
    float dot = 0.f, ss = 0.f;
#pragma unroll
    for (int i = 0; i < 8; i++) {
        float4 kv = k[i * 32 + lane];
        float4 qv = q[i * 32 + lane];
        dot += kv.x * qv.x + kv.y * qv.y + kv.z * qv.z + kv.w * qv.w;
        ss  += kv.x * kv.x + kv.y * kv.y + kv.z * kv.z + kv.w * kv.w;
    }
#pragma unroll
    for (int o = 16; o > 0; o >>= 1) {
        dot += __shfl_xor_sync(0xffffffffu, dot, o);
        ss  += __shfl_xor_sync(0xffffffffu, ss, o);
    }
    if (lane == 0) {
        g_logits[b][r] = dot * 0.03125f;
        if (r >= 1) g_ninv[b][r - 1] = rsqrtf(ss + 1e-12f);
    }
}

// ---------------- K2: softmax over 577, top-L rank select, complement ----------------
__global__ __launch_bounds__(640) void k_softmax_topk() {
    __shared__ float sl[NK];
    __shared__ float sa[NTOK];
    __shared__ int   sflag[NTOK];
    __shared__ float red[640];
    int b = blockIdx.x;
    int t = threadIdx.x;

    if (t == 0) g_cnt[b] = 0;      // reset last-block ticket for k_final
    if (t < NK) sl[t] = g_logits[b][t];
    __syncthreads();

    red[t] = (t < NK) ? sl[t] : -FLT_MAX;
    __syncthreads();
    if (t < 128) red[t] = fmaxf(red[t], red[t + 512]);
    __syncthreads();
    for (int s = 256; s > 0; s >>= 1) {
        if (t < s) red[t] = fmaxf(red[t], red[t + s]);
        __syncthreads();
    }
    float mx = red[0];
    __syncthreads();

    float e = 0.f;
    if (t < NK) { e = expf(sl[t] - mx); }
    red[t] = e;
    __syncthreads();
    if (t < 128) red[t] += red[t + 512];
    __syncthreads();
    for (int s = 256; s > 0; s >>= 1) {
        if (t < s) red[t] += red[t + s];
        __syncthreads();
    }
    float inv_sum = 1.0f / red[0];
    __syncthreads();

    if (t >= 1 && t < NK) {
        float a = e * inv_sum;
        sa[t - 1] = a;
        g_attn[b][t - 1] = a;
    }
    __syncthreads();

    // rank = #(greater) + #(equal, lower index): exact jax.lax.top_k order
    if (t < NTOK) {
        float my = sa[t];
        int cnt = 0;
        for (int m = 0; m < NTOK; m++) {
            float v = sa[m];
            cnt += (v > my) || (v == my && m < t);
        }
        sflag[t] = (cnt < LTOP);
        if (cnt < LTOP) g_idx[b][cnt] = t;
    }
    __syncthreads();

    if (t < NTOK && !sflag[t]) {
        int nb = 0;
        for (int m = 0; m < t; m++) nb += sflag[m];
        g_compl[b][t - nb] = t;
    }
}

// ---------------- K3: sim GEMM, mma.sync tf32 3-split, splitK=8 for occupancy ----------
// Block: M=80 x N=192 x K=128 (4 BK=32 stages). 8 warps x 24-wide N strips.
#define SIM_BN 192
#define LDA 36
#define BUF_F 9792                    // A 80*36 + B 192*36
#define OFF_B_REG 2880
#define OFF_IDX (2 * BUF_F)
#define SIM_SMEM_BYTES ((OFF_IDX + 80) * 4)
#define TF32_MASK 0xffffe000u
#define NCHUNK 2176                   // (80 + 192) rows * 8 float4
#define NSTAGE 4                      // 128 / 32

__device__ __forceinline__ void mma_tf32(float* c, const uint32_t* a, const uint32_t* bb) {
    asm volatile(
        "mma.sync.aligned.m16n8k8.row.col.f32.tf32.tf32.f32 "
        "{%0,%1,%2,%3}, {%4,%5,%6,%7}, {%8,%9}, {%0,%1,%2,%3};"
        : "+f"(c[0]), "+f"(c[1]), "+f"(c[2]), "+f"(c[3])
        : "r"(a[0]), "r"(a[1]), "r"(a[2]), "r"(a[3]), "r"(bb[0]), "r"(bb[1]));
}

__global__ __launch_bounds__(256, 2) void k_sim_mma(const float* __restrict__ keys) {
    extern __shared__ float sm[];
    int* sidx = (int*)(sm + OFF_IDX);
    uint32_t sbase = smem_u32(sm);
    int tid = threadIdx.x;
    int b  = blockIdx.y;
    int n0 = blockIdx.x * SIM_BN;
    int kz = blockIdx.z;

    if (tid < LTOP) sidx[tid] = g_idx[b][tid];
    __syncthreads();

    const float* kb = keys + (size_t)b * NK * CH;

    // loader precompute: 9 float4-chunks per thread (last conditional)
    uint32_t goff[9];   // float offset into kb (incl. kz*128 + c4*4)
    uint32_t soff[9];   // float offset within buffer
#pragma unroll
    for (int i = 0; i < 9; i++) {
        int q = tid + 256 * i;
        int qq = (q < NCHUNK) ? q : 0;
        if (qq < 640) {
            int row = qq >> 3, c4 = qq & 7;
            int tok = (row < LTOP) ? sidx[row] : sidx[0];
            goff[i] = (uint32_t)((tok + 1) * CH + kz * 128 + c4 * 4);
            soff[i] = (uint32_t)(row * LDA + c4 * 4);
        } else {
            int q2 = qq - 640;
            int row = q2 >> 3, c4 = q2 & 7;
            goff[i] = (uint32_t)((1 + n0 + row) * CH + kz * 128 + c4 * 4);
            soff[i] = (uint32_t)(OFF_B_REG + row * LDA + c4 * 4);
        }
    }

    int w = tid >> 5, lane = tid & 31;
    int g = lane >> 2, t4 = lane & 3;
    int nb = w * 24;

    float acc[5][3][4];
#pragma unroll
    for (int i = 0; i < 5; i++)
#pragma unroll
        for (int j = 0; j < 3; j++)
#pragma unroll
            for (int c = 0; c < 4; c++) acc[i][j][c] = 0.f;

    auto issue = [&](int s, int bf) {
        uint32_t sadd = s * 32;
        uint32_t badd = (uint32_t)(bf * BUF_F);
#pragma unroll
        for (int i = 0; i < 8; i++)
            CP_ASYNC16(sbase + 4 * (badd + soff[i]), kb + goff[i] + sadd);
        if (tid < NCHUNK - 2048)
            CP_ASYNC16(sbase + 4 * (badd + soff[8]), kb + goff[8] + sadd);
        CP_COMMIT();
    };

    issue(0, 0);
    for (int s = 0; s < NSTAGE; s++) {
        int bf = s & 1;
        if (s < NSTAGE - 1) { issue(s + 1, bf ^ 1); CP_WAIT(1); }
        else                { CP_WAIT(0); }
        __syncthreads();

        const float* bufA = sm + bf * BUF_F;
        const float* bufB = bufA + OFF_B_REG;
#pragma unroll
        for (int s8 = 0; s8 < 4; s8++) {
            int kk = s8 * 8;
            uint32_t bh[3][2], bl[3][2];
#pragma unroll
            for (int j = 0; j < 3; j++) {
                int base = (nb + j * 8 + g) * LDA + kk + t4;
                float r0 = bufB[base], r1 = bufB[base + 4];
                uint32_t h0 = __float_as_uint(r0) & TF32_MASK;
                uint32_t h1 = __float_as_uint(r1) & TF32_MASK;
                bh[j][0] = h0; bl[j][0] = __float_as_uint(r0 - __uint_as_float(h0));
                bh[j][1] = h1; bl[j][1] = __float_as_uint(r1 - __uint_as_float(h1));
            }
#pragma unroll
            for (int mt = 0; mt < 5; mt++) {
                int ab = (mt * 16 + g) * LDA + kk + t4;
                float a0 = bufA[ab], a1 = bufA[ab + 8 * LDA], a2 = bufA[ab + 4], a3 = bufA[ab + 8 * LDA + 4];
                uint32_t ah[4], al[4];
                ah[0] = __float_as_uint(a0) & TF32_MASK; al[0] = __float_as_uint(a0 - __uint_as_float(ah[0]));
                ah[1] = __float_as_uint(a1) & TF32_MASK; al[1] = __float_as_uint(a1 - __uint_as_float(ah[1]));
                ah[2] = __float_as_uint(a2) & TF32_MASK; al[2] = __float_as_uint(a2 - __uint_as_float(ah[2]));
                ah[3] = __float_as_uint(a3) & TF32_MASK; al[3] = __float_as_uint(a3 - __uint_as_float(ah[3]));
#pragma unroll
                for (int j = 0; j < 3; j++) {
                    mma_tf32(acc[mt][j], ah, bh[j]);
                    mma_tf32(acc[mt][j], ah, bl[j]);
                    mma_tf32(acc[mt][j], al, bh[j]);
                }
            }
        }
        __syncthreads();
    }

    float* base = &g_sim[kz][0][0][0];
#pragma unroll
    for (int mt = 0; mt < 5; mt++) {
        int m0 = mt * 16 + g;
        int m1 = m0 + 8;
#pragma unroll
        for (int j = 0; j < 3; j++) {
            int n = n0 + nb + j * 8 + 2 * t4;
            if (m0 < LTOP)
                *(float2*)&base[((size_t)b * LTOP + m0) * NTOK + n] = make_float2(acc[mt][j][0], acc[mt][j][1]);
            if (m1 < LTOP)
                *(float2*)&base[((size_t)b * LTOP + m1) * NTOK + n] = make_float2(acc[mt][j][2], acc[mt][j][3]);
        }
    }
}

// ---------------- K4: selection+merge rows, segmented extra row (grid 84 x 32) ----------
__device__ __forceinline__ unsigned long long umax64(unsigned long long a, unsigned long long b) { return a > b ? a : b; }
__device__ __forceinline__ unsigned long long umin64(unsigned long long a, unsigned long long b) { return a < b ? a : b; }

#define FIN_SMEM_BYTES (16 * 4096)   // 4 slots x 4 rows x 4KB

template<int NROWS>
__device__ __forceinline__ void gather_rows(const float4* __restrict__ xb,
                                            const int* rows, const float* ws,
                                            float* smf, uint32_t sb, int t, float4& acc) {
    const int G = (NROWS + 3) >> 2;
    auto issue = [&](int gg) {
        int r0 = gg * 4;
#pragma unroll
        for (int i = 0; i < 4; i++) {
            int r = r0 + i;
            if (r < NROWS) {
                uint32_t dst = sb + (uint32_t)(((gg & 3) * 4 + i) * 4096 + t * 16);
                CP_ASYNC16(dst, xb + (size_t)rows[r] * 256 + t);
            }
        }
        CP_COMMIT();
    };
    issue(0);
    if (G > 1) issue(1);
    if (G > 2) issue(2);
    for (int gg = 0; gg < G; gg++) {
        if (gg + 3 < G) { issue(gg + 3); CP_WAIT(2); }
        else            { CP_WAIT(0); }
#pragma unroll
        for (int i = 0; i < 4; i++) {
            int r = gg * 4 + i;
            if (r < NROWS) {
                float4 v = ((const float4*)smf)[((gg & 3) * 4 + i) * 256 + t];
                float wj = ws[r];
                acc.x += wj * v.x; acc.y += wj * v.y; acc.z += wj * v.z; acc.w += wj * v.w;
            }
        }
    }
}

__global__ __launch_bounds__(256) void k_final(const float* __restrict__ x,
                                               float* __restrict__ out) {
    extern __shared__ float smf[];
    __shared__ int   ssel[KCL > SEGTOK ? KCL : SEGTOK];
    __shared__ float sw[KCL > SEGTOK ? KCL : SEGTOK];
    __shared__ int   s_last;
    uint32_t sb = smem_u32(smf);
    int b = blockIdx.y;
    int l = blockIdx.x;
    int t = threadIdx.x;
    const float4* xb = (const float4*)(x + (size_t)b * NTOK * CH);

    if (l >= LTOP) {
        int s = l - LTOP;
        if (t < SEGTOK) {
            int tok = g_compl[b][s * SEGTOK + t];
            ssel[t] = tok;
            sw[t]   = g_attn[b][tok];
        }
        __syncthreads();
        float4 acc = make_float4(0.f, 0.f, 0.f, 0.f);
        gather_rows<SEGTOK>(xb, ssel, sw, smf, sb, t, acc);
        ((float4*)&g_xpart[b][s][0])[t] = acc;

        __threadfence();
        __syncthreads();
        if (t == 0) s_last = (atomicAdd(&g_cnt[b], 1) == NSEG - 1);
        __syncthreads();
        if (s_last) {
            float4 r = make_float4(0.f, 0.f, 0.f, 0.f);
#pragma unroll
            for (int ss = 0; ss < NSEG; ss++) {
                float4 v = ((const float4*)&g_xpart[b][ss][0])[t];
                r.x += v.x; r.y += v.y; r.z += v.z; r.w += v.w;
            }
            ((float4*)(out + ((size_t)b * (LTOP + 1) + LTOP) * CH))[t] = r;
        }
        return;
    }

    int idxl = g_idx[b][l];
    float4 acc = xb[(size_t)idxl * 256 + t];   // base row load overlaps warp0 selection

    if (t < 32) {
        int lane = t;
        const float* __restrict__ pn = &g_ninv[b][0];
        const float* p[KSPLIT];
#pragma unroll
        for (int ss = 0; ss < KSPLIT; ss++) p[ss] = &g_sim[ss][b][l][0];

        unsigned long long key[18];
        unsigned long long s0 = 0, s1 = 0, s2 = 0, s3 = 0;
#pragma unroll
        for (int j = 0; j < 18; j++) {
            int m = lane + 32 * j;
            float v = ((p[0][m] + p[1][m]) + (p[2][m] + p[3][m]))
                    + ((p[4][m] + p[5][m]) + (p[6][m] + p[7][m]));
            v *= pn[m];
            unsigned u = __float_as_uint(v);
            u = (u & 0x80000000u) ? ~u : (u | 0x80000000u);
            unsigned long long kk = ((unsigned long long)u << 32) | (unsigned)(NTOK - m);
            if (m == idxl) kk = 0ULL;
            key[j] = kk;
            unsigned long long t0 = umax64(s0, kk), b0 = umin64(s0, kk); s0 = t0;
            unsigned long long t1 = umax64(s1, b0), b1 = umin64(s1, b0); s1 = t1;
            unsigned long long t2 = umax64(s2, b1), b2 = umin64(s2, b1); s2 = t2;
            s3 = umax64(s3, b2);
        }

        int c = 0;
        unsigned long long cand = s0;
        for (int it = 0; it < KCL; it++) {
            uint32_t chi = (uint32_t)(cand >> 32);
            uint32_t mhi = __reduce_max_sync(0xffffffffu, chi);
            uint32_t lom = (chi == mhi) ? (uint32_t)cand : 0u;
            uint32_t mlo = __reduce_max_sync(0xffffffffu, lom);
            unsigned long long wmax = ((unsigned long long)mhi << 32) | mlo;
            if (cand == wmax) {
                ssel[it] = NTOK - (int)mlo;
                c++;
                if (c == 1)      cand = s1;
                else if (c == 2) cand = s2;
                else if (c == 3) cand = s3;
                else {
                    unsigned long long nf = 0;
#pragma unroll
                    for (int j = 0; j < 18; j++)
                        if (key[j] < wmax) nf = umax64(nf, key[j]);
                    cand = nf;
                }
            }
        }
        __syncwarp();
        sw[lane] = g_attn[b][ssel[lane]];
    }
    __syncthreads();

    gather_rows<KCL>(xb, ssel, sw, smf, sb, t, acc);
    ((float4*)(out + ((size_t)b * (LTOP + 1) + l) * CH))[t] = acc;
}

// ---------------- launch: 4 graph nodes (k_final lands in ncu sample slot 3) ------------
extern "C" void kernel_launch(void* const* d_in, const int* in_sizes, int n_in,
                              void* d_out, int out_size) {
    const float* x       = (const float*)d_in[0];   // image_features [32,576,1024]
    const float* keys    = (const float*)d_in[1];   // keys           [32,577,1024]
    const float* queries = (const float*)d_in[2];   // queries        [32,577,1024]
    float* out = (float*)d_out;                     // [32,73,1024]

    static int init_done = 0;
    if (!init_done) {
        cudaFuncSetAttribute(k_sim_mma, cudaFuncAttributeMaxDynamicSharedMemorySize, SIM_SMEM_BYTES);
        cudaFuncSetAttribute(k_final, cudaFuncAttributeMaxDynamicSharedMemorySize, FIN_SMEM_BYTES);
        init_done = 1;
    }

    int nwarps = BATCH * NK;
    k_logits<<<(nwarps * 32 + 255) / 256, 256>>>(keys, queries);
    k_softmax_topk<<<BATCH, 640>>>();
    dim3 g2(NTOK / SIM_BN, BATCH, KSPLIT);          // 3 x 32 x 8 = 768 blocks
    k_sim_mma<<<g2, 256, SIM_SMEM_BYTES>>>(keys);
    dim3 g3(LTOP + NSEG, BATCH);                    // 84 x 32 = 2688 blocks  (ncu slot 3)
    k_final<<<g3, 256, FIN_SMEM_BYTES>>>(x, out);
}

// round 14
// speedup vs baseline: 1.1687x; 1.1687x over previous
#include <cuda_runtime.h>
#include <math.h>
#include <float.h>
#include <stdint.h>

#define BATCH 32
#define NTOK  576
#define NK    577      // N + 1 (with CLS)
#define CH    1024
#define LTOP  72       // N/8
#define NCOMPL 504     // N - L
#define KCL   32
#define NSEG  12
#define SEGTOK (NCOMPL / NSEG)   // 42
#define KSPLIT 4

// ---------------- device scratch (static, allocation-free) ----------------
__device__ float g_logits[BATCH][NK];
__device__ float g_ninv[BATCH][NTOK];
__device__ float g_attn[BATCH][NTOK];
__device__ int   g_idx[BATCH][LTOP];
__device__ int   g_compl[BATCH][NCOMPL];
__device__ float g_sim[KSPLIT][BATCH][LTOP][NTOK];
__device__ float g_xpart[BATCH][NSEG][CH];
__device__ int   g_cnt[BATCH];

#define CP_ASYNC16(dst, src) \
    asm volatile("cp.async.cg.shared.global [%0], [%1], 16;" :: "r"(dst), "l"(src) : "memory")
#define CP_COMMIT() asm volatile("cp.async.commit_group;" ::: "memory")
#define CP_WAIT(n)  asm volatile("cp.async.wait_group %0;" :: "n"(n) : "memory")

__device__ __forceinline__ uint32_t smem_u32(const void* p) {
    uint32_t a;
    asm("{ .reg .u64 t; cvta.to.shared.u64 t, %1; cvt.u32.u64 %0, t; }" : "=r"(a) : "l"(p));
    return a;
}

// ---------------- K1: logits (q0 . key_r) and per-row inv-norms (grid-wide) -------------
__global__ __launch_bounds__(256) void k_logits(const float* __restrict__ keys,
                                                const float* __restrict__ queries) {
    int gw   = (blockIdx.x * blockDim.x + threadIdx.x) >> 5;
    int lane = threadIdx.x & 31;
    if (gw >= BATCH * NK) return;
    int b = gw / NK;
    int r = gw - b * NK;
    const float4* q = (const float4*)(queries + (size_t)b * NK * CH);
    const float4* k = (const float4*)(keys + ((size_t)b * NK + r) * CH);
    float dot = 0.f, ss = 0.f;
#pragma unroll
    for (int i = 0; i < 8; i++) {
        float4 kv = k[i * 32 + lane];
        float4 qv = q[i * 32 + lane];
        dot += kv.x * qv.x + kv.y * qv.y + kv.z * qv.z + kv.w * qv.w;
        ss  += kv.x * kv.x + kv.y * kv.y + kv.z * kv.z + kv.w * kv.w;
    }
#pragma unroll
    for (int o = 16; o > 0; o >>= 1) {
        dot += __shfl_xor_sync(0xffffffffu, dot, o);
        ss  += __shfl_xor_sync(0xffffffffu, ss, o);
    }
    if (lane == 0) {
        g_logits[b][r] = dot * 0.03125f;
        if (r >= 1) g_ninv[b][r - 1] = rsqrtf(ss + 1e-12f);
    }
}

// ---------------- K2: softmax over 577, top-L rank select, complement ----------------
__global__ __launch_bounds__(640) void k_softmax_topk() {
    __shared__ float sl[NK];
    __shared__ float sa[NTOK];
    __shared__ int   sflag[NTOK];
    __shared__ float red[640];
    int b = blockIdx.x;
    int t = threadIdx.x;

    if (t == 0) g_cnt[b] = 0;      // reset last-block ticket for k_final
    if (t < NK) sl[t] = g_logits[b][t];
    __syncthreads();

    red[t] = (t < NK) ? sl[t] : -FLT_MAX;
    __syncthreads();
    if (t < 128) red[t] = fmaxf(red[t], red[t + 512]);
    __syncthreads();
    for (int s = 256; s > 0; s >>= 1) {
        if (t < s) red[t] = fmaxf(red[t], red[t + s]);
        __syncthreads();
    }
    float mx = red[0];
    __syncthreads();

    float e = 0.f;
    if (t < NK) { e = expf(sl[t] - mx); }
    red[t] = e;
    __syncthreads();
    if (t < 128) red[t] += red[t + 512];
    __syncthreads();
    for (int s = 256; s > 0; s >>= 1) {
        if (t < s) red[t] += red[t + s];
        __syncthreads();
    }
    float inv_sum = 1.0f / red[0];
    __syncthreads();

    if (t >= 1 && t < NK) {
        float a = e * inv_sum;
        sa[t - 1] = a;
        g_attn[b][t - 1] = a;
    }
    __syncthreads();

    // rank = #(greater) + #(equal, lower index): exact jax.lax.top_k order
    if (t < NTOK) {
        float my = sa[t];
        int cnt = 0;
        for (int m = 0; m < NTOK; m++) {
            float v = sa[m];
            cnt += (v > my) || (v == my && m < t);
        }
        sflag[t] = (cnt < LTOP);
        if (cnt < LTOP) g_idx[b][cnt] = t;
    }
    __syncthreads();

    if (t < NTOK && !sflag[t]) {
        int nb = 0;
        for (int m = 0; m < t; m++) nb += sflag[m];
        g_compl[b][t - nb] = t;
    }
}

// ---------------- K3: sim GEMM, mma.sync tf32 3-split, splitK=4 (R12 proven) -----------
// Block: M=80 x N=192 x K=256 (8 BK=32 stages). 8 warps x 24-wide N strips.
#define SIM_BN 192
#define LDA 36
#define BUF_F 9792                    // A 80*36 + B 192*36
#define OFF_B_REG 2880
#define OFF_IDX (2 * BUF_F)
#define SIM_SMEM_BYTES ((OFF_IDX + 80) * 4)
#define TF32_MASK 0xffffe000u
#define NCHUNK 2176                   // (80 + 192) rows * 8 float4
#define NSTAGE 8                      // 256 / 32

__device__ __forceinline__ void mma_tf32(float* c, const uint32_t* a, const uint32_t* bb) {
    asm volatile(
        "mma.sync.aligned.m16n8k8.row.col.f32.tf32.tf32.f32 "
        "{%0,%1,%2,%3}, {%4,%5,%6,%7}, {%8,%9}, {%0,%1,%2,%3};"
        : "+f"(c[0]), "+f"(c[1]), "+f"(c[2]), "+f"(c[3])
        : "r"(a[0]), "r"(a[1]), "r"(a[2]), "r"(a[3]), "r"(bb[0]), "r"(bb[1]));
}

__global__ __launch_bounds__(256, 2) void k_sim_mma(const float* __restrict__ keys) {
    extern __shared__ float sm[];
    int* sidx = (int*)(sm + OFF_IDX);
    uint32_t sbase = smem_u32(sm);
    int tid = threadIdx.x;
    int b  = blockIdx.y;
    int n0 = blockIdx.x * SIM_BN;
    int kz = blockIdx.z;

    if (tid < LTOP) sidx[tid] = g_idx[b][tid];
    __syncthreads();

    const float* kb = keys + (size_t)b * NK * CH;

    uint32_t goff[9];
    uint32_t soff[9];
#pragma unroll
    for (int i = 0; i < 9; i++) {
        int q = tid + 256 * i;
        int qq = (q < NCHUNK) ? q : 0;
        if (qq < 640) {
            int row = qq >> 3, c4 = qq & 7;
            int tok = (row < LTOP) ? sidx[row] : sidx[0];
            goff[i] = (uint32_t)((tok + 1) * CH + kz * 256 + c4 * 4);
            soff[i] = (uint32_t)(row * LDA + c4 * 4);
        } else {
            int q2 = qq - 640;
            int row = q2 >> 3, c4 = q2 & 7;
            goff[i] = (uint32_t)((1 + n0 + row) * CH + kz * 256 + c4 * 4);
            soff[i] = (uint32_t)(OFF_B_REG + row * LDA + c4 * 4);
        }
    }

    int w = tid >> 5, lane = tid & 31;
    int g = lane >> 2, t4 = lane & 3;
    int nb = w * 24;

    float acc[5][3][4];
#pragma unroll
    for (int i = 0; i < 5; i++)
#pragma unroll
        for (int j = 0; j < 3; j++)
#pragma unroll
            for (int c = 0; c < 4; c++) acc[i][j][c] = 0.f;

    auto issue = [&](int s, int bf) {
        uint32_t sadd = s * 32;
        uint32_t badd = (uint32_t)(bf * BUF_F);
#pragma unroll
        for (int i = 0; i < 8; i++)
            CP_ASYNC16(sbase + 4 * (badd + soff[i]), kb + goff[i] + sadd);
        if (tid < NCHUNK - 2048)
            CP_ASYNC16(sbase + 4 * (badd + soff[8]), kb + goff[8] + sadd);
        CP_COMMIT();
    };

    issue(0, 0);
    for (int s = 0; s < NSTAGE; s++) {
        int bf = s & 1;
        if (s < NSTAGE - 1) { issue(s + 1, bf ^ 1); CP_WAIT(1); }
        else                { CP_WAIT(0); }
        __syncthreads();

        const float* bufA = sm + bf * BUF_F;
        const float* bufB = bufA + OFF_B_REG;
#pragma unroll
        for (int s8 = 0; s8 < 4; s8++) {
            int kk = s8 * 8;
            uint32_t bh[3][2], bl[3][2];
#pragma unroll
            for (int j = 0; j < 3; j++) {
                int base = (nb + j * 8 + g) * LDA + kk + t4;
                float r0 = bufB[base], r1 = bufB[base + 4];
                uint32_t h0 = __float_as_uint(r0) & TF32_MASK;
                uint32_t h1 = __float_as_uint(r1) & TF32_MASK;
                bh[j][0] = h0; bl[j][0] = __float_as_uint(r0 - __uint_as_float(h0));
                bh[j][1] = h1; bl[j][1] = __float_as_uint(r1 - __uint_as_float(h1));
            }
#pragma unroll
            for (int mt = 0; mt < 5; mt++) {
                int ab = (mt * 16 + g) * LDA + kk + t4;
                float a0 = bufA[ab], a1 = bufA[ab + 8 * LDA], a2 = bufA[ab + 4], a3 = bufA[ab + 8 * LDA + 4];
                uint32_t ah[4], al[4];
                ah[0] = __float_as_uint(a0) & TF32_MASK; al[0] = __float_as_uint(a0 - __uint_as_float(ah[0]));
                ah[1] = __float_as_uint(a1) & TF32_MASK; al[1] = __float_as_uint(a1 - __uint_as_float(ah[1]));
                ah[2] = __float_as_uint(a2) & TF32_MASK; al[2] = __float_as_uint(a2 - __uint_as_float(ah[2]));
                ah[3] = __float_as_uint(a3) & TF32_MASK; al[3] = __float_as_uint(a3 - __uint_as_float(ah[3]));
#pragma unroll
                for (int j = 0; j < 3; j++) {
                    mma_tf32(acc[mt][j], ah, bh[j]);
                    mma_tf32(acc[mt][j], ah, bl[j]);
                    mma_tf32(acc[mt][j], al, bh[j]);
                }
            }
        }
        __syncthreads();
    }

    float* base = &g_sim[kz][0][0][0];
#pragma unroll
    for (int mt = 0; mt < 5; mt++) {
        int m0 = mt * 16 + g;
        int m1 = m0 + 8;
#pragma unroll
        for (int j = 0; j < 3; j++) {
            int n = n0 + nb + j * 8 + 2 * t4;
            if (m0 < LTOP)
                *(float2*)&base[((size_t)b * LTOP + m0) * NTOK + n] = make_float2(acc[mt][j][0], acc[mt][j][1]);
            if (m1 < LTOP)
                *(float2*)&base[((size_t)b * LTOP + m1) * NTOK + n] = make_float2(acc[mt][j][2], acc[mt][j][3]);
        }
    }
}

// ---------------- K4: selection+merge rows, segmented extra row (grid 84 x 32) ----------
// Plain-LDG gather (no dynamic smem -> higher occupancy; unroll-8 MLP).
__device__ __forceinline__ unsigned long long umax64(unsigned long long a, unsigned long long b) { return a > b ? a : b; }
__device__ __forceinline__ unsigned long long umin64(unsigned long long a, unsigned long long b) { return a < b ? a : b; }

__global__ __launch_bounds__(256) void k_final(const float* __restrict__ x,
                                               float* __restrict__ out) {
    __shared__ int   ssel[KCL > SEGTOK ? KCL : SEGTOK];
    __shared__ float sw[KCL > SEGTOK ? KCL : SEGTOK];
    __shared__ int   s_last;
    int b = blockIdx.y;
    int l = blockIdx.x;
    int t = threadIdx.x;
    const float4* xb = (const float4*)(x + (size_t)b * NTOK * CH);

    if (l >= LTOP) {
        // ---- extra-row segment: 42 tokens -> partial; last block per batch reduces ----
        int s = l - LTOP;
        if (t < SEGTOK) {
            int tok = g_compl[b][s * SEGTOK + t];
            ssel[t] = tok;
            sw[t]   = g_attn[b][tok];
        }
        __syncthreads();
        float4 acc = make_float4(0.f, 0.f, 0.f, 0.f);
#pragma unroll 6
        for (int j = 0; j < SEGTOK; j++) {
            float4 v = xb[(size_t)ssel[j] * 256 + t];
            float wj = sw[j];
            acc.x += wj * v.x; acc.y += wj * v.y; acc.z += wj * v.z; acc.w += wj * v.w;
        }
        ((float4*)&g_xpart[b][s][0])[t] = acc;

        __threadfence();
        __syncthreads();
        if (t == 0) s_last = (atomicAdd(&g_cnt[b], 1) == NSEG - 1);
        __syncthreads();
        if (s_last) {
            float4 r = make_float4(0.f, 0.f, 0.f, 0.f);
#pragma unroll
            for (int ss = 0; ss < NSEG; ss++) {
                float4 v = ((const float4*)&g_xpart[b][ss][0])[t];
                r.x += v.x; r.y += v.y; r.z += v.z; r.w += v.w;
            }
            ((float4*)(out + ((size_t)b * (LTOP + 1) + LTOP) * CH))[t] = r;
        }
        return;
    }

    // ---- merged row l: warp-0 top-32 selection, then block-wide plain gather ----
    int idxl = g_idx[b][l];
    float4 acc = xb[(size_t)idxl * 256 + t];   // base row load overlaps warp0 selection

    if (t < 32) {
        int lane = t;
        const float* __restrict__ pn = &g_ninv[b][0];
        const float* __restrict__ p0 = &g_sim[0][b][l][0];
        const float* __restrict__ p1 = &g_sim[1][b][l][0];
        const float* __restrict__ p2 = &g_sim[2][b][l][0];
        const float* __restrict__ p3 = &g_sim[3][b][l][0];

        unsigned long long key[18];
        unsigned long long s0 = 0, s1 = 0, s2 = 0, s3 = 0;
#pragma unroll
        for (int j = 0; j < 18; j++) {
            int m = lane + 32 * j;
            float v = ((p0[m] + p1[m]) + (p2[m] + p3[m])) * pn[m];
            unsigned u = __float_as_uint(v);
            u = (u & 0x80000000u) ? ~u : (u | 0x80000000u);
            unsigned long long kk = ((unsigned long long)u << 32) | (unsigned)(NTOK - m);
            if (m == idxl) kk = 0ULL;
            key[j] = kk;
            unsigned long long t0 = umax64(s0, kk), b0 = umin64(s0, kk); s0 = t0;
            unsigned long long t1 = umax64(s1, b0), b1 = umin64(s1, b0); s1 = t1;
            unsigned long long t2 = umax64(s2, b1), b2 = umin64(s2, b1); s2 = t2;
            s3 = umax64(s3, b2);
        }

        int c = 0;
        unsigned long long cand = s0;
        for (int it = 0; it < KCL; it++) {
            uint32_t chi = (uint32_t)(cand >> 32);
            uint32_t mhi = __reduce_max_sync(0xffffffffu, chi);
            uint32_t lom = (chi == mhi) ? (uint32_t)cand : 0u;
            uint32_t mlo = __reduce_max_sync(0xffffffffu, lom);
            unsigned long long wmax = ((unsigned long long)mhi << 32) | mlo;
            if (cand == wmax) {
                ssel[it] = NTOK - (int)mlo;
                c++;
                if (c == 1)      cand = s1;
                else if (c == 2) cand = s2;
                else if (c == 3) cand = s3;
                else {
                    unsigned long long nf = 0;
#pragma unroll
                    for (int j = 0; j < 18; j++)
                        if (key[j] < wmax) nf = umax64(nf, key[j]);
                    cand = nf;
                }
            }
        }
        __syncwarp();
        sw[lane] = g_attn[b][ssel[lane]];
    }
    __syncthreads();

#pragma unroll 8
    for (int j = 0; j < KCL; j++) {
        float4 v = xb[(size_t)ssel[j] * 256 + t];
        float wj = sw[j];
        acc.x += wj * v.x; acc.y += wj * v.y; acc.z += wj * v.z; acc.w += wj * v.w;
    }
    ((float4*)(out + ((size_t)b * (LTOP + 1) + l) * CH))[t] = acc;
}

// ---------------- launch: 4 graph nodes (k_final lands in ncu sample slot 3) ------------
extern "C" void kernel_launch(void* const* d_in, const int* in_sizes, int n_in,
                              void* d_out, int out_size) {
    const float* x       = (const float*)d_in[0];   // image_features [32,576,1024]
    const float* keys    = (const float*)d_in[1];   // keys           [32,577,1024]
    const float* queries = (const float*)d_in[2];   // queries        [32,577,1024]
    float* out = (float*)d_out;                     // [32,73,1024]

    static int init_done = 0;
    if (!init_done) {
        cudaFuncSetAttribute(k_sim_mma, cudaFuncAttributeMaxDynamicSharedMemorySize, SIM_SMEM_BYTES);
        init_done = 1;
    }

    int nwarps = BATCH * NK;
    k_logits<<<(nwarps * 32 + 255) / 256, 256>>>(keys, queries);
    k_softmax_topk<<<BATCH, 640>>>();
    dim3 g2(NTOK / SIM_BN, BATCH, KSPLIT);          // 3 x 32 x 4 = 384 blocks
    k_sim_mma<<<g2, 256, SIM_SMEM_BYTES>>>(keys);
    dim3 g3(LTOP + NSEG, BATCH);                    // 84 x 32 = 2688 blocks  (ncu slot 3)
    k_final<<<g3, 256>>>(x, out);
}

// round 15
// speedup vs baseline: 1.1711x; 1.0020x over previous
#include <cuda_runtime.h>
#include <math.h>
#include <float.h>
#include <stdint.h>

#define BATCH 32
#define NTOK  576
#define NK    577      // N + 1 (with CLS)
#define CH    1024
#define LTOP  72       // N/8
#define NCOMPL 504     // N - L
#define KCL   32
#define NSEG  12
#define SEGTOK (NCOMPL / NSEG)   // 42
#define KSPLIT 4

// ---------------- device scratch (static, allocation-free) ----------------
__device__ float g_logits[BATCH][NK];
__device__ float g_ninv[BATCH][NTOK];
__device__ float g_attn[BATCH][NTOK];
__device__ int   g_idx[BATCH][LTOP];
__device__ int   g_compl[BATCH][NCOMPL];
__device__ float g_sim[KSPLIT][BATCH][LTOP][NTOK];
__device__ float g_xpart[BATCH][NSEG][CH];
__device__ int   g_cnt[BATCH];

#define CP_ASYNC16(dst, src) \
    asm volatile("cp.async.cg.shared.global [%0], [%1], 16;" :: "r"(dst), "l"(src) : "memory")
#define CP_COMMIT() asm volatile("cp.async.commit_group;" ::: "memory")
#define CP_WAIT(n)  asm volatile("cp.async.wait_group %0;" :: "n"(n) : "memory")

__device__ __forceinline__ uint32_t smem_u32(const void* p) {
    uint32_t a;
    asm("{ .reg .u64 t; cvta.to.shared.u64 t, %1; cvt.u32.u64 %0, t; }" : "=r"(a) : "l"(p));
    return a;
}

// ---------------- K1: logits (q0 . key_r) and per-row inv-norms (grid-wide) -------------
__global__ __launch_bounds__(256) void k_logits(const float* __restrict__ keys,
                                                const float* __restrict__ queries) {
    int gw   = (blockIdx.x * blockDim.x + threadIdx.x) >> 5;
    int lane = threadIdx.x & 31;
    if (gw >= BATCH * NK) return;
    int b = gw / NK;
    int r = gw - b * NK;
    const float4* q = (const float4*)(queries + (size_t)b * NK * CH);
    const float4* k = (const float4*)(keys + ((size_t)b * NK + r) * CH);
    float dot = 0.f, ss = 0.f;
#pragma unroll
    for (int i = 0; i < 8; i++) {
        float4 kv = k[i * 32 + lane];
        float4 qv = q[i * 32 + lane];
        dot += kv.x * qv.x + kv.y * qv.y + kv.z * qv.z + kv.w * qv.w;
        ss  += kv.x * kv.x + kv.y * kv.y + kv.z * kv.z + kv.w * kv.w;
    }
#pragma unroll
    for (int o = 16; o > 0; o >>= 1) {
        dot += __shfl_xor_sync(0xffffffffu, dot, o);
        ss  += __shfl_xor_sync(0xffffffffu, ss, o);
    }
    if (lane == 0) {
        g_logits[b][r] = dot * 0.03125f;
        if (r >= 1) g_ninv[b][r - 1] = rsqrtf(ss + 1e-12f);
    }
}

// ---------------- K2: softmax over 577, top-L rank select, complement ----------------
__global__ __launch_bounds__(640) void k_softmax_topk() {
    __shared__ float sl[NK];
    __shared__ float sa[NTOK];
    __shared__ int   sflag[NTOK];
    __shared__ float red[640];
    int b = blockIdx.x;
    int t = threadIdx.x;

    if (t == 0) g_cnt[b] = 0;      // reset last-block ticket for k_final
    if (t < NK) sl[t] = g_logits[b][t];
    __syncthreads();

    red[t] = (t < NK) ? sl[t] : -FLT_MAX;
    __syncthreads();
    if (t < 128) red[t] = fmaxf(red[t], red[t + 512]);
    __syncthreads();
    for (int s = 256; s > 0; s >>= 1) {
        if (t < s) red[t] = fmaxf(red[t], red[t + s]);
        __syncthreads();
    }
    float mx = red[0];
    __syncthreads();

    float e = 0.f;
    if (t < NK) { e = expf(sl[t] - mx); }
    red[t] = e;
    __syncthreads();
    if (t < 128) red[t] += red[t + 512];
    __syncthreads();
    for (int s = 256; s > 0; s >>= 1) {
        if (t < s) red[t] += red[t + s];
        __syncthreads();
    }
    float inv_sum = 1.0f / red[0];
    __syncthreads();

    if (t >= 1 && t < NK) {
        float a = e * inv_sum;
        sa[t - 1] = a;
        g_attn[b][t - 1] = a;
    }
    __syncthreads();

    // rank = #(greater) + #(equal, lower index): exact jax.lax.top_k order
    if (t < NTOK) {
        float my = sa[t];
        int cnt = 0;
        for (int m = 0; m < NTOK; m++) {
            float v = sa[m];
            cnt += (v > my) || (v == my && m < t);
        }
        sflag[t] = (cnt < LTOP);
        if (cnt < LTOP) g_idx[b][cnt] = t;
    }
    __syncthreads();

    if (t < NTOK && !sflag[t]) {
        int nb = 0;
        for (int m = 0; m < t; m++) nb += sflag[m];
        g_compl[b][t - nb] = t;
    }
}

// ---------------- K3: sim GEMM, mma.sync tf32 3-split, term-major MMA order -------------
// Block: M=80 x N=192 x K=256 (8 BK=32 stages). 8 warps x 24-wide N strips.
// Same-accumulator MMA reuse distance raised 1 -> 9/6 to hide HMMA RAW latency.
#define SIM_BN 192
#define LDA 36
#define BUF_F 9792                    // A 80*36 + B 192*36
#define OFF_B_REG 2880
#define OFF_IDX (2 * BUF_F)
#define SIM_SMEM_BYTES ((OFF_IDX + 80) * 4)
#define TF32_MASK 0xffffe000u
#define NCHUNK 2176                   // (80 + 192) rows * 8 float4
#define NSTAGE 8                      // 256 / 32

__device__ __forceinline__ void mma_tf32(float* c, const uint32_t* a, const uint32_t* bb) {
    asm volatile(
        "mma.sync.aligned.m16n8k8.row.col.f32.tf32.tf32.f32 "
        "{%0,%1,%2,%3}, {%4,%5,%6,%7}, {%8,%9}, {%0,%1,%2,%3};"
        : "+f"(c[0]), "+f"(c[1]), "+f"(c[2]), "+f"(c[3])
        : "r"(a[0]), "r"(a[1]), "r"(a[2]), "r"(a[3]), "r"(bb[0]), "r"(bb[1]));
}

__global__ __launch_bounds__(256, 2) void k_sim_mma(const float* __restrict__ keys) {
    extern __shared__ float sm[];
    int* sidx = (int*)(sm + OFF_IDX);
    uint32_t sbase = smem_u32(sm);
    int tid = threadIdx.x;
    int b  = blockIdx.y;
    int n0 = blockIdx.x * SIM_BN;
    int kz = blockIdx.z;

    if (tid < LTOP) sidx[tid] = g_idx[b][tid];
    __syncthreads();

    const float* kb = keys + (size_t)b * NK * CH;

    uint32_t goff[9];
    uint32_t soff[9];
#pragma unroll
    for (int i = 0; i < 9; i++) {
        int q = tid + 256 * i;
        int qq = (q < NCHUNK) ? q : 0;
        if (qq < 640) {
            int row = qq >> 3, c4 = qq & 7;
            int tok = (row < LTOP) ? sidx[row] : sidx[0];
            goff[i] = (uint32_t)((tok + 1) * CH + kz * 256 + c4 * 4);
            soff[i] = (uint32_t)(row * LDA + c4 * 4);
        } else {
            int q2 = qq - 640;
            int row = q2 >> 3, c4 = q2 & 7;
            goff[i] = (uint32_t)((1 + n0 + row) * CH + kz * 256 + c4 * 4);
            soff[i] = (uint32_t)(OFF_B_REG + row * LDA + c4 * 4);
        }
    }

    int w = tid >> 5, lane = tid & 31;
    int g = lane >> 2, t4 = lane & 3;
    int nb = w * 24;

    float acc[5][3][4];
#pragma unroll
    for (int i = 0; i < 5; i++)
#pragma unroll
        for (int j = 0; j < 3; j++)
#pragma unroll
            for (int c = 0; c < 4; c++) acc[i][j][c] = 0.f;

    auto issue = [&](int s, int bf) {
        uint32_t sadd = s * 32;
        uint32_t badd = (uint32_t)(bf * BUF_F);
#pragma unroll
        for (int i = 0; i < 8; i++)
            CP_ASYNC16(sbase + 4 * (badd + soff[i]), kb + goff[i] + sadd);
        if (tid < NCHUNK - 2048)
            CP_ASYNC16(sbase + 4 * (badd + soff[8]), kb + goff[8] + sadd);
        CP_COMMIT();
    };

    issue(0, 0);
    for (int s = 0; s < NSTAGE; s++) {
        int bf = s & 1;
        if (s < NSTAGE - 1) { issue(s + 1, bf ^ 1); CP_WAIT(1); }
        else                { CP_WAIT(0); }
        __syncthreads();

        const float* bufA = sm + bf * BUF_F;
        const float* bufB = bufA + OFF_B_REG;
#pragma unroll
        for (int s8 = 0; s8 < 4; s8++) {
            int kk = s8 * 8;
            uint32_t bh[3][2], bl[3][2];
#pragma unroll
            for (int j = 0; j < 3; j++) {
                int base = (nb + j * 8 + g) * LDA + kk + t4;
                float r0 = bufB[base], r1 = bufB[base + 4];
                uint32_t h0 = __float_as_uint(r0) & TF32_MASK;
                uint32_t h1 = __float_as_uint(r1) & TF32_MASK;
                bh[j][0] = h0; bl[j][0] = __float_as_uint(r0 - __uint_as_float(h0));
                bh[j][1] = h1; bl[j][1] = __float_as_uint(r1 - __uint_as_float(h1));
            }
            // --- mt group {0,1,2}: load A frags, then term-major MMAs (distance 9) ---
            uint32_t ah[3][4], al[3][4];
#pragma unroll
            for (int mi = 0; mi < 3; mi++) {
                int ab = (mi * 16 + g) * LDA + kk + t4;
                float a0 = bufA[ab], a1 = bufA[ab + 8 * LDA], a2 = bufA[ab + 4], a3 = bufA[ab + 8 * LDA + 4];
                ah[mi][0] = __float_as_uint(a0) & TF32_MASK; al[mi][0] = __float_as_uint(a0 - __uint_as_float(ah[mi][0]));
                ah[mi][1] = __float_as_uint(a1) & TF32_MASK; al[mi][1] = __float_as_uint(a1 - __uint_as_float(ah[mi][1]));
                ah[mi][2] = __float_as_uint(a2) & TF32_MASK; al[mi][2] = __float_as_uint(a2 - __uint_as_float(ah[mi][2]));
                ah[mi][3] = __float_as_uint(a3) & TF32_MASK; al[mi][3] = __float_as_uint(a3 - __uint_as_float(ah[mi][3]));
            }
#pragma unroll
            for (int mi = 0; mi < 3; mi++)
#pragma unroll
                for (int j = 0; j < 3; j++) mma_tf32(acc[mi][j], ah[mi], bh[j]);
#pragma unroll
            for (int mi = 0; mi < 3; mi++)
#pragma unroll
                for (int j = 0; j < 3; j++) mma_tf32(acc[mi][j], ah[mi], bl[j]);
#pragma unroll
            for (int mi = 0; mi < 3; mi++)
#pragma unroll
                for (int j = 0; j < 3; j++) mma_tf32(acc[mi][j], al[mi], bh[j]);

            // --- mt group {3,4}: reuse frag registers (distance 6) ---
#pragma unroll
            for (int mi = 0; mi < 2; mi++) {
                int ab = ((mi + 3) * 16 + g) * LDA + kk + t4;
                float a0 = bufA[ab], a1 = bufA[ab + 8 * LDA], a2 = bufA[ab + 4], a3 = bufA[ab + 8 * LDA + 4];
                ah[mi][0] = __float_as_uint(a0) & TF32_MASK; al[mi][0] = __float_as_uint(a0 - __uint_as_float(ah[mi][0]));
                ah[mi][1] = __float_as_uint(a1) & TF32_MASK; al[mi][1] = __float_as_uint(a1 - __uint_as_float(ah[mi][1]));
                ah[mi][2] = __float_as_uint(a2) & TF32_MASK; al[mi][2] = __float_as_uint(a2 - __uint_as_float(ah[mi][2]));
                ah[mi][3] = __float_as_uint(a3) & TF32_MASK; al[mi][3] = __float_as_uint(a3 - __uint_as_float(ah[mi][3]));
            }
#pragma unroll
            for (int mi = 0; mi < 2; mi++)
#pragma unroll
                for (int j = 0; j < 3; j++) mma_tf32(acc[mi + 3][j], ah[mi], bh[j]);
#pragma unroll
            for (int mi = 0; mi < 2; mi++)
#pragma unroll
                for (int j = 0; j < 3; j++) mma_tf32(acc[mi + 3][j], ah[mi], bl[j]);
#pragma unroll
            for (int mi = 0; mi < 2; mi++)
#pragma unroll
                for (int j = 0; j < 3; j++) mma_tf32(acc[mi + 3][j], al[mi], bh[j]);
        }
        __syncthreads();
    }

    float* base = &g_sim[kz][0][0][0];
#pragma unroll
    for (int mt = 0; mt < 5; mt++) {
        int m0 = mt * 16 + g;
        int m1 = m0 + 8;
#pragma unroll
        for (int j = 0; j < 3; j++) {
            int n = n0 + nb + j * 8 + 2 * t4;
            if (m0 < LTOP)
                *(float2*)&base[((size_t)b * LTOP + m0) * NTOK + n] = make_float2(acc[mt][j][0], acc[mt][j][1]);
            if (m1 < LTOP)
                *(float2*)&base[((size_t)b * LTOP + m1) * NTOK + n] = make_float2(acc[mt][j][2], acc[mt][j][3]);
        }
    }
}

// ---------------- K4: selection+merge rows, segmented extra row (grid 84 x 32) ----------
__device__ __forceinline__ unsigned long long umax64(unsigned long long a, unsigned long long b) { return a > b ? a : b; }
__device__ __forceinline__ unsigned long long umin64(unsigned long long a, unsigned long long b) { return a < b ? a : b; }

__global__ __launch_bounds__(256) void k_final(const float* __restrict__ x,
                                               float* __restrict__ out) {
    __shared__ int   ssel[KCL > SEGTOK ? KCL : SEGTOK];
    __shared__ float sw[KCL > SEGTOK ? KCL : SEGTOK];
    __shared__ int   s_last;
    int b = blockIdx.y;
    int l = blockIdx.x;
    int t = threadIdx.x;
    const float4* xb = (const float4*)(x + (size_t)b * NTOK * CH);

    if (l >= LTOP) {
        // ---- extra-row segment: 42 tokens -> partial; last block per batch reduces ----
        int s = l - LTOP;
        if (t < SEGTOK) {
            int tok = g_compl[b][s * SEGTOK + t];
            ssel[t] = tok;
            sw[t]   = g_attn[b][tok];
        }
        __syncthreads();
        float4 acc = make_float4(0.f, 0.f, 0.f, 0.f);
#pragma unroll 6
        for (int j = 0; j < SEGTOK; j++) {
            float4 v = xb[(size_t)ssel[j] * 256 + t];
            float wj = sw[j];
            acc.x += wj * v.x; acc.y += wj * v.y; acc.z += wj * v.z; acc.w += wj * v.w;
        }
        ((float4*)&g_xpart[b][s][0])[t] = acc;

        __threadfence();
        __syncthreads();
        if (t == 0) s_last = (atomicAdd(&g_cnt[b], 1) == NSEG - 1);
        __syncthreads();
        if (s_last) {
            float4 r = make_float4(0.f, 0.f, 0.f, 0.f);
#pragma unroll
            for (int ss = 0; ss < NSEG; ss++) {
                float4 v = ((const float4*)&g_xpart[b][ss][0])[t];
                r.x += v.x; r.y += v.y; r.z += v.z; r.w += v.w;
            }
            ((float4*)(out + ((size_t)b * (LTOP + 1) + LTOP) * CH))[t] = r;
        }
        return;
    }

    // ---- merged row l: warp-0 top-32 selection, then block-wide plain gather ----
    int idxl = g_idx[b][l];
    float4 acc = xb[(size_t)idxl * 256 + t];   // base row load overlaps warp0 selection

    if (t < 32) {
        int lane = t;
        const float* __restrict__ pn = &g_ninv[b][0];
        const float* __restrict__ p0 = &g_sim[0][b][l][0];
        const float* __restrict__ p1 = &g_sim[1][b][l][0];
        const float* __restrict__ p2 = &g_sim[2][b][l][0];
        const float* __restrict__ p3 = &g_sim[3][b][l][0];

        unsigned long long key[18];
        unsigned long long s0 = 0, s1 = 0, s2 = 0, s3 = 0;
#pragma unroll
        for (int j = 0; j < 18; j++) {
            int m = lane + 32 * j;
            float v = ((p0[m] + p1[m]) + (p2[m] + p3[m])) * pn[m];
            unsigned u = __float_as_uint(v);
            u = (u & 0x80000000u) ? ~u : (u | 0x80000000u);
            unsigned long long kk = ((unsigned long long)u << 32) | (unsigned)(NTOK - m);
            if (m == idxl) kk = 0ULL;
            key[j] = kk;
            unsigned long long t0 = umax64(s0, kk), b0 = umin64(s0, kk); s0 = t0;
            unsigned long long t1 = umax64(s1, b0), b1 = umin64(s1, b0); s1 = t1;
            unsigned long long t2 = umax64(s2, b1), b2 = umin64(s2, b1); s2 = t2;
            s3 = umax64(s3, b2);
        }

        int c = 0;
        unsigned long long cand = s0;
        for (int it = 0; it < KCL; it++) {
            uint32_t chi = (uint32_t)(cand >> 32);
            uint32_t mhi = __reduce_max_sync(0xffffffffu, chi);
            uint32_t lom = (chi == mhi) ? (uint32_t)cand : 0u;
            uint32_t mlo = __reduce_max_sync(0xffffffffu, lom);
            unsigned long long wmax = ((unsigned long long)mhi << 32) | mlo;
            if (cand == wmax) {
                ssel[it] = NTOK - (int)mlo;
                c++;
                if (c == 1)      cand = s1;
                else if (c == 2) cand = s2;
                else if (c == 3) cand = s3;
                else {
                    unsigned long long nf = 0;
#pragma unroll
                    for (int j = 0; j < 18; j++)
                        if (key[j] < wmax) nf = umax64(nf, key[j]);
                    cand = nf;
                }
            }
        }
        __syncwarp();
        sw[lane] = g_attn[b][ssel[lane]];
    }
    __syncthreads();

#pragma unroll 8
    for (int j = 0; j < KCL; j++) {
        float4 v = xb[(size_t)ssel[j] * 256 + t];
        float wj = sw[j];
        acc.x += wj * v.x; acc.y += wj * v.y; acc.z += wj * v.z; acc.w += wj * v.w;
    }
    ((float4*)(out + ((size_t)b * (LTOP + 1) + l) * CH))[t] = acc;
}

// ---------------- launch: 4 graph nodes ----------------
extern "C" void kernel_launch(void* const* d_in, const int* in_sizes, int n_in,
                              void* d_out, int out_size) {
    const float* x       = (const float*)d_in[0];   // image_features [32,576,1024]
    const float* keys    = (const float*)d_in[1];   // keys           [32,577,1024]
    const float* queries = (const float*)d_in[2];   // queries        [32,577,1024]
    float* out = (float*)d_out;                     // [32,73,1024]

    static int init_done = 0;
    if (!init_done) {
        cudaFuncSetAttribute(k_sim_mma, cudaFuncAttributeMaxDynamicSharedMemorySize, SIM_SMEM_BYTES);
        init_done = 1;
    }

    int nwarps = BATCH * NK;
    k_logits<<<(nwarps * 32 + 255) / 256, 256>>>(keys, queries);
    k_softmax_topk<<<BATCH, 640>>>();
    dim3 g2(NTOK / SIM_BN, BATCH, KSPLIT);          // 3 x 32 x 4 = 384 blocks
    k_sim_mma<<<g2, 256, SIM_SMEM_BYTES>>>(keys);
    dim3 g3(LTOP + NSEG, BATCH);                    // 84 x 32 = 2688 blocks
    k_final<<<g3, 256>>>(x, out);
}

// round 16
// speedup vs baseline: 1.2158x; 1.0382x over previous
#include <cuda_runtime.h>
#include <math.h>
#include <float.h>
#include <stdint.h>

#define BATCH 32
#define NTOK  576
#define NK    577      // N + 1 (with CLS)
#define CH    1024
#define LTOP  72       // N/8
#define NCOMPL 504     // N - L
#define KCL   32
#define NSEG  12
#define SEGTOK (NCOMPL / NSEG)   // 42
#define KSPLIT 4

// ---------------- device scratch (static, allocation-free) ----------------
__device__ float g_logits[BATCH][NK];
__device__ float g_ninv[BATCH][NTOK];
__device__ float g_attn[BATCH][NTOK];
__device__ int   g_idx[BATCH][LTOP];
__device__ int   g_compl[BATCH][NCOMPL];
__device__ float g_sim[KSPLIT][BATCH][LTOP][NTOK];
__device__ float g_xpart[BATCH][NSEG][CH];
__device__ int   g_cnt[BATCH];

#define CP_ASYNC16(dst, src) \
    asm volatile("cp.async.cg.shared.global [%0], [%1], 16;" :: "r"(dst), "l"(src) : "memory")
#define CP_COMMIT() asm volatile("cp.async.commit_group;" ::: "memory")
#define CP_WAIT(n)  asm volatile("cp.async.wait_group %0;" :: "n"(n) : "memory")

__device__ __forceinline__ uint32_t smem_u32(const void* p) {
    uint32_t a;
    asm("{ .reg .u64 t; cvta.to.shared.u64 t, %1; cvt.u32.u64 %0, t; }" : "=r"(a) : "l"(p));
    return a;
}

// ---------------- K1: logits (q0 . key_r) and per-row inv-norms (grid-wide) -------------
__global__ __launch_bounds__(256) void k_logits(const float* __restrict__ keys,
                                                const float* __restrict__ queries) {
    int gw   = (blockIdx.x * blockDim.x + threadIdx.x) >> 5;
    int lane = threadIdx.x & 31;
    if (gw >= BATCH * NK) return;
    int b = gw / NK;
    int r = gw - b * NK;
    const float4* q = (const float4*)(queries + (size_t)b * NK * CH);
    const float4* k = (const float4*)(keys + ((size_t)b * NK + r) * CH);
    float dot = 0.f, ss = 0.f;
#pragma unroll
    for (int i = 0; i < 8; i++) {
        float4 kv = k[i * 32 + lane];
        float4 qv = q[i * 32 + lane];
        dot += kv.x * qv.x + kv.y * qv.y + kv.z * qv.z + kv.w * qv.w;
        ss  += kv.x * kv.x + kv.y * kv.y + kv.z * kv.z + kv.w * kv.w;
    }
#pragma unroll
    for (int o = 16; o > 0; o >>= 1) {
        dot += __shfl_xor_sync(0xffffffffu, dot, o);
        ss  += __shfl_xor_sync(0xffffffffu, ss, o);
    }
    if (lane == 0) {
        g_logits[b][r] = dot * 0.03125f;
        if (r >= 1) g_ninv[b][r - 1] = rsqrtf(ss + 1e-12f);
    }
}

// ---------------- K2: softmax over 577, top-L rank select, complement ----------------
__global__ __launch_bounds__(640) void k_softmax_topk() {
    __shared__ float sl[NK];
    __shared__ float sa[NTOK];
    __shared__ int   sflag[NTOK];
    __shared__ float red[640];
    int b = blockIdx.x;
    int t = threadIdx.x;

    if (t == 0) g_cnt[b] = 0;      // reset last-block ticket for k_final
    if (t < NK) sl[t] = g_logits[b][t];
    __syncthreads();

    red[t] = (t < NK) ? sl[t] : -FLT_MAX;
    __syncthreads();
    if (t < 128) red[t] = fmaxf(red[t], red[t + 512]);
    __syncthreads();
    for (int s = 256; s > 0; s >>= 1) {
        if (t < s) red[t] = fmaxf(red[t], red[t + s]);
        __syncthreads();
    }
    float mx = red[0];
    __syncthreads();

    float e = 0.f;
    if (t < NK) { e = expf(sl[t] - mx); }
    red[t] = e;
    __syncthreads();
    if (t < 128) red[t] += red[t + 512];
    __syncthreads();
    for (int s = 256; s > 0; s >>= 1) {
        if (t < s) red[t] += red[t + s];
        __syncthreads();
    }
    float inv_sum = 1.0f / red[0];
    __syncthreads();

    if (t >= 1 && t < NK) {
        float a = e * inv_sum;
        sa[t - 1] = a;
        g_attn[b][t - 1] = a;
    }
    __syncthreads();

    // rank = #(greater) + #(equal, lower index): exact jax.lax.top_k order
    if (t < NTOK) {
        float my = sa[t];
        int cnt = 0;
        for (int m = 0; m < NTOK; m++) {
            float v = sa[m];
            cnt += (v > my) || (v == my && m < t);
        }
        sflag[t] = (cnt < LTOP);
        if (cnt < LTOP) g_idx[b][cnt] = t;
    }
    __syncthreads();

    if (t < NTOK && !sflag[t]) {
        int nb = 0;
        for (int m = 0; m < t; m++) nb += sflag[m];
        g_compl[b][t - nb] = t;
    }
}

// ---------------- K3: sim GEMM, mma.sync tf32 3-split, splitK=4 (R12/R15 proven) --------
#define SIM_BN 192
#define LDA 36
#define BUF_F 9792                    // A 80*36 + B 192*36
#define OFF_B_REG 2880
#define OFF_IDX (2 * BUF_F)
#define SIM_SMEM_BYTES ((OFF_IDX + 80) * 4)
#define TF32_MASK 0xffffe000u
#define NCHUNK 2176                   // (80 + 192) rows * 8 float4
#define NSTAGE 8                      // 256 / 32

__device__ __forceinline__ void mma_tf32(float* c, const uint32_t* a, const uint32_t* bb) {
    asm volatile(
        "mma.sync.aligned.m16n8k8.row.col.f32.tf32.tf32.f32 "
        "{%0,%1,%2,%3}, {%4,%5,%6,%7}, {%8,%9}, {%0,%1,%2,%3};"
        : "+f"(c[0]), "+f"(c[1]), "+f"(c[2]), "+f"(c[3])
        : "r"(a[0]), "r"(a[1]), "r"(a[2]), "r"(a[3]), "r"(bb[0]), "r"(bb[1]));
}

__global__ __launch_bounds__(256, 2) void k_sim_mma(const float* __restrict__ keys) {
    extern __shared__ float sm[];
    int* sidx = (int*)(sm + OFF_IDX);
    uint32_t sbase = smem_u32(sm);
    int tid = threadIdx.x;
    int b  = blockIdx.y;
    int n0 = blockIdx.x * SIM_BN;
    int kz = blockIdx.z;

    if (tid < LTOP) sidx[tid] = g_idx[b][tid];
    __syncthreads();

    const float* kb = keys + (size_t)b * NK * CH;

    uint32_t goff[9];
    uint32_t soff[9];
#pragma unroll
    for (int i = 0; i < 9; i++) {
        int q = tid + 256 * i;
        int qq = (q < NCHUNK) ? q : 0;
        if (qq < 640) {
            int row = qq >> 3, c4 = qq & 7;
            int tok = (row < LTOP) ? sidx[row] : sidx[0];
            goff[i] = (uint32_t)((tok + 1) * CH + kz * 256 + c4 * 4);
            soff[i] = (uint32_t)(row * LDA + c4 * 4);
        } else {
            int q2 = qq - 640;
            int row = q2 >> 3, c4 = q2 & 7;
            goff[i] = (uint32_t)((1 + n0 + row) * CH + kz * 256 + c4 * 4);
            soff[i] = (uint32_t)(OFF_B_REG + row * LDA + c4 * 4);
        }
    }

    int w = tid >> 5, lane = tid & 31;
    int g = lane >> 2, t4 = lane & 3;
    int nb = w * 24;

    float acc[5][3][4];
#pragma unroll
    for (int i = 0; i < 5; i++)
#pragma unroll
        for (int j = 0; j < 3; j++)
#pragma unroll
            for (int c = 0; c < 4; c++) acc[i][j][c] = 0.f;

    auto issue = [&](int s, int bf) {
        uint32_t sadd = s * 32;
        uint32_t badd = (uint32_t)(bf * BUF_F);
#pragma unroll
        for (int i = 0; i < 8; i++)
            CP_ASYNC16(sbase + 4 * (badd + soff[i]), kb + goff[i] + sadd);
        if (tid < NCHUNK - 2048)
            CP_ASYNC16(sbase + 4 * (badd + soff[8]), kb + goff[8] + sadd);
        CP_COMMIT();
    };

    issue(0, 0);
    for (int s = 0; s < NSTAGE; s++) {
        int bf = s & 1;
        if (s < NSTAGE - 1) { issue(s + 1, bf ^ 1); CP_WAIT(1); }
        else                { CP_WAIT(0); }
        __syncthreads();

        const float* bufA = sm + bf * BUF_F;
        const float* bufB = bufA + OFF_B_REG;
#pragma unroll
        for (int s8 = 0; s8 < 4; s8++) {
            int kk = s8 * 8;
            uint32_t bh[3][2], bl[3][2];
#pragma unroll
            for (int j = 0; j < 3; j++) {
                int base = (nb + j * 8 + g) * LDA + kk + t4;
                float r0 = bufB[base], r1 = bufB[base + 4];
                uint32_t h0 = __float_as_uint(r0) & TF32_MASK;
                uint32_t h1 = __float_as_uint(r1) & TF32_MASK;
                bh[j][0] = h0; bl[j][0] = __float_as_uint(r0 - __uint_as_float(h0));
                bh[j][1] = h1; bl[j][1] = __float_as_uint(r1 - __uint_as_float(h1));
            }
#pragma unroll
            for (int mt = 0; mt < 5; mt++) {
                int ab = (mt * 16 + g) * LDA + kk + t4;
                float a0 = bufA[ab], a1 = bufA[ab + 8 * LDA], a2 = bufA[ab + 4], a3 = bufA[ab + 8 * LDA + 4];
                uint32_t ah[4], al[4];
                ah[0] = __float_as_uint(a0) & TF32_MASK; al[0] = __float_as_uint(a0 - __uint_as_float(ah[0]));
                ah[1] = __float_as_uint(a1) & TF32_MASK; al[1] = __float_as_uint(a1 - __uint_as_float(ah[1]));
                ah[2] = __float_as_uint(a2) & TF32_MASK; al[2] = __float_as_uint(a2 - __uint_as_float(ah[2]));
                ah[3] = __float_as_uint(a3) & TF32_MASK; al[3] = __float_as_uint(a3 - __uint_as_float(ah[3]));
#pragma unroll
                for (int j = 0; j < 3; j++) {
                    mma_tf32(acc[mt][j], ah, bh[j]);
                    mma_tf32(acc[mt][j], ah, bl[j]);
                    mma_tf32(acc[mt][j], al, bh[j]);
                }
            }
        }
        __syncthreads();
    }

    float* base = &g_sim[kz][0][0][0];
#pragma unroll
    for (int mt = 0; mt < 5; mt++) {
        int m0 = mt * 16 + g;
        int m1 = m0 + 8;
#pragma unroll
        for (int j = 0; j < 3; j++) {
            int n = n0 + nb + j * 8 + 2 * t4;
            if (m0 < LTOP)
                *(float2*)&base[((size_t)b * LTOP + m0) * NTOK + n] = make_float2(acc[mt][j][0], acc[mt][j][1]);
            if (m1 < LTOP)
                *(float2*)&base[((size_t)b * LTOP + m1) * NTOK + n] = make_float2(acc[mt][j][2], acc[mt][j][3]);
        }
    }
}

// ---------------- K4: selection+merge rows, segmented extra row (grid 84 x 32) ----------
// Block-parallel key-gen into smem; warp-0 selection reads keys via LDS (low regs).
__device__ __forceinline__ unsigned long long umax64(unsigned long long a, unsigned long long b) { return a > b ? a : b; }
__device__ __forceinline__ unsigned long long umin64(unsigned long long a, unsigned long long b) { return a < b ? a : b; }

__global__ __launch_bounds__(256) void k_final(const float* __restrict__ x,
                                               float* __restrict__ out) {
    __shared__ unsigned long long skey[NTOK];
    __shared__ int   ssel[KCL > SEGTOK ? KCL : SEGTOK];
    __shared__ float sw[KCL > SEGTOK ? KCL : SEGTOK];
    __shared__ int   s_last;
    int b = blockIdx.y;
    int l = blockIdx.x;
    int t = threadIdx.x;
    const float4* xb = (const float4*)(x + (size_t)b * NTOK * CH);

    if (l >= LTOP) {
        // ---- extra-row segment: 42 tokens -> partial; last block per batch reduces ----
        int s = l - LTOP;
        if (t < SEGTOK) {
            int tok = g_compl[b][s * SEGTOK + t];
            ssel[t] = tok;
            sw[t]   = g_attn[b][tok];
        }
        __syncthreads();
        float4 acc = make_float4(0.f, 0.f, 0.f, 0.f);
#pragma unroll 6
        for (int j = 0; j < SEGTOK; j++) {
            float4 v = xb[(size_t)ssel[j] * 256 + t];
            float wj = sw[j];
            acc.x += wj * v.x; acc.y += wj * v.y; acc.z += wj * v.z; acc.w += wj * v.w;
        }
        ((float4*)&g_xpart[b][s][0])[t] = acc;

        __threadfence();
        __syncthreads();
        if (t == 0) s_last = (atomicAdd(&g_cnt[b], 1) == NSEG - 1);
        __syncthreads();
        if (s_last) {
            float4 r = make_float4(0.f, 0.f, 0.f, 0.f);
#pragma unroll
            for (int ss = 0; ss < NSEG; ss++) {
                float4 v = ((const float4*)&g_xpart[b][ss][0])[t];
                r.x += v.x; r.y += v.y; r.z += v.z; r.w += v.w;
            }
            ((float4*)(out + ((size_t)b * (LTOP + 1) + LTOP) * CH))[t] = r;
        }
        return;
    }

    // ---- merged row l ----
    int idxl = g_idx[b][l];
    float4 acc = xb[(size_t)idxl * 256 + t];   // base row load overlaps key-gen

    // block-parallel key generation (576 keys, 2-3 per thread)
    {
        const float* __restrict__ pn = &g_ninv[b][0];
        const float* __restrict__ p0 = &g_sim[0][b][l][0];
        const float* __restrict__ p1 = &g_sim[1][b][l][0];
        const float* __restrict__ p2 = &g_sim[2][b][l][0];
        const float* __restrict__ p3 = &g_sim[3][b][l][0];
#pragma unroll
        for (int r = 0; r < 3; r++) {
            int m = t + r * 256;
            if (m < NTOK) {
                float v = ((p0[m] + p1[m]) + (p2[m] + p3[m])) * pn[m];
                unsigned u = __float_as_uint(v);
                u = (u & 0x80000000u) ? ~u : (u | 0x80000000u);
                unsigned long long kk = ((unsigned long long)u << 32) | (unsigned)(NTOK - m);
                if (m == idxl) kk = 0ULL;
                skey[m] = kk;
            }
        }
    }
    __syncthreads();

    if (t < 32) {
        int lane = t;
        // sorted top-4 per lane from smem keys
        unsigned long long s0 = 0, s1 = 0, s2 = 0, s3 = 0;
#pragma unroll
        for (int j = 0; j < 18; j++) {
            unsigned long long kk = skey[lane + 32 * j];
            unsigned long long t0 = umax64(s0, kk), b0 = umin64(s0, kk); s0 = t0;
            unsigned long long t1 = umax64(s1, b0), b1 = umin64(s1, b0); s1 = t1;
            unsigned long long t2 = umax64(s2, b1), b2 = umin64(s2, b1); s2 = t2;
            s3 = umax64(s3, b2);
        }

        int c = 0;
        unsigned long long cand = s0;
        for (int it = 0; it < KCL; it++) {
            uint32_t chi = (uint32_t)(cand >> 32);
            uint32_t mhi = __reduce_max_sync(0xffffffffu, chi);
            uint32_t lom = (chi == mhi) ? (uint32_t)cand : 0u;
            uint32_t mlo = __reduce_max_sync(0xffffffffu, lom);
            unsigned long long wmax = ((unsigned long long)mhi << 32) | mlo;
            if (cand == wmax) {            // unique winner (index embedded)
                ssel[it] = NTOK - (int)mlo;
                c++;
                if (c == 1)      cand = s1;
                else if (c == 2) cand = s2;
                else if (c == 3) cand = s3;
                else {
                    unsigned long long nf = 0;
#pragma unroll
                    for (int j = 0; j < 18; j++) {
                        unsigned long long kk = skey[lane + 32 * j];
                        if (kk < wmax) nf = umax64(nf, kk);
                    }
                    cand = nf;
                }
            }
        }
        __syncwarp();
        sw[lane] = g_attn[b][ssel[lane]];
    }
    __syncthreads();

#pragma unroll 8
    for (int j = 0; j < KCL; j++) {
        float4 v = xb[(size_t)ssel[j] * 256 + t];
        float wj = sw[j];
        acc.x += wj * v.x; acc.y += wj * v.y; acc.z += wj * v.z; acc.w += wj * v.w;
    }
    ((float4*)(out + ((size_t)b * (LTOP + 1) + l) * CH))[t] = acc;
}

// ---------------- launch: 4 graph nodes ----------------
extern "C" void kernel_launch(void* const* d_in, const int* in_sizes, int n_in,
                              void* d_out, int out_size) {
    const float* x       = (const float*)d_in[0];   // image_features [32,576,1024]
    const float* keys    = (const float*)d_in[1];   // keys           [32,577,1024]
    const float* queries = (const float*)d_in[2];   // queries        [32,577,1024]
    float* out = (float*)d_out;                     // [32,73,1024]

    static int init_done = 0;
    if (!init_done) {
        cudaFuncSetAttribute(k_sim_mma, cudaFuncAttributeMaxDynamicSharedMemorySize, SIM_SMEM_BYTES);
        init_done = 1;
    }

    int nwarps = BATCH * NK;
    k_logits<<<(nwarps * 32 + 255) / 256, 256>>>(keys, queries);
    k_softmax_topk<<<BATCH, 640>>>();
    dim3 g2(NTOK / SIM_BN, BATCH, KSPLIT);          // 3 x 32 x 4 = 384 blocks
    k_sim_mma<<<g2, 256, SIM_SMEM_BYTES>>>(keys);
    dim3 g3(LTOP + NSEG, BATCH);                    // 84 x 32 = 2688 blocks
    k_final<<<g3, 256>>>(x, out);
}